// round 9
// baseline (speedup 1.0000x reference)
#include <cuda_runtime.h>
#include <cuda_fp16.h>
#include <cstdint>

static constexpr int MAXN = 100352;              // multiple of 8
static constexpr int SMEM_BYTES = MAXN * 2;      // 196KB fp16 value array
static constexpr int NBLOCKS = 148;              // <= SM count (GB300: 152) -> co-resident
static constexpr int NTHREADS = 1024;

// Scratch (static device globals: allocation-free per harness rules)
__device__ float  g_h0[MAXN];     // dropout1(x)
__device__ float  g_deg[MAXN];    // in-degree (float)
__device__ float  g_dinv[MAXN];   // deg^-1/2 (0 if deg==0)
__device__ __half g_hd16[MAXN];   // h0 * dinv   (fp16)
__device__ float  g_acc1[MAXN];   // edge-sum for conv1
__device__ __half g_sd16[MAXN];   // s2 * dinv   (fp16)
__device__ float  g_acc2[MAXN];   // edge-sum for conv2
__device__ unsigned int g_ctr;    // monotonic grid-barrier counter (never reset)

// keep  <=>  uniform(bits) < float32(0.4)  <=>  bits < 0x66666800
#define KEEP_THRESH 0x66666800u

__host__ __device__ __forceinline__ void tf2x32(uint32_t k0, uint32_t k1,
                                                uint32_t x0, uint32_t x1,
                                                uint32_t& o0, uint32_t& o1) {
    uint32_t ks2 = k0 ^ k1 ^ 0x1BD11BDAu;
    x0 += k0; x1 += k1;
#define TF_ROT(d) { x0 += x1; x1 = (x1 << (d)) | (x1 >> (32 - (d))); x1 ^= x0; }
    TF_ROT(13) TF_ROT(15) TF_ROT(26) TF_ROT(6)   x0 += k1;  x1 += ks2 + 1u;
    TF_ROT(17) TF_ROT(29) TF_ROT(16) TF_ROT(24)  x0 += ks2; x1 += k0 + 2u;
    TF_ROT(13) TF_ROT(15) TF_ROT(26) TF_ROT(6)   x0 += k0;  x1 += k1 + 3u;
    TF_ROT(17) TF_ROT(29) TF_ROT(16) TF_ROT(24)  x0 += k1;  x1 += ks2 + 4u;
    TF_ROT(13) TF_ROT(15) TF_ROT(26) TF_ROT(6)   x0 += ks2; x1 += k0 + 5u;
#undef TF_ROT
    o0 = x0; o1 = x1;
}

__device__ __forceinline__ uint32_t rbits32(uint32_t k0, uint32_t k1, uint32_t i) {
    uint32_t a, b;
    tf2x32(k0, k1, 0u, i, a, b);
    return a ^ b;
}

// Software grid barrier. All NBLOCKS blocks are co-resident (196KB smem ->
// 1 block/SM, grid <= SM count), so spinning is starvation-free. Counter is
// monotonic across barriers AND graph replays; each wait's target is derived
// from the returned ticket, so no reset is ever needed.
__device__ __forceinline__ void gridbar() {
    __syncthreads();
    if (threadIdx.x == 0) {
        __threadfence();  // release: make our REDs/stores globally visible
        unsigned t = atomicAdd(&g_ctr, 1u);
        unsigned target = (t / NBLOCKS + 1u) * NBLOCKS;
        while (*(volatile unsigned*)&g_ctr < target) __nanosleep(64);
        __threadfence();  // acquire
    }
    __syncthreads();
}

__global__ __launch_bounds__(NTHREADS, 1) void k_fused(
    const float* __restrict__ x,
    const int* __restrict__ src, const int* __restrict__ dst,
    const float* __restrict__ W1, const float* __restrict__ b1,
    const float* __restrict__ W2, const float* __restrict__ b2,
    float* __restrict__ out, int N, int E,
    uint32_t k1a, uint32_t k1b, uint32_t k2a, uint32_t k2b)
{
    extern __shared__ __half s_val[];
    const int tid    = blockIdx.x * NTHREADS + threadIdx.x;
    const int stride = NBLOCKS * NTHREADS;
    const int EV8    = E >> 3;
    const int4* s4 = reinterpret_cast<const int4*>(src);
    const int4* d4 = reinterpret_cast<const int4*>(dst);

    // ---- P0: dropout1 + zero accumulators ----
    for (int n = tid; n < N; n += stride) {
        uint32_t bits = rbits32(k1a, k1b, (uint32_t)n);
        g_h0[n]   = (bits < KEEP_THRESH) ? (x[n] / 0.4f) : 0.0f;
        g_deg[n]  = 0.0f;
        g_acc1[n] = 0.0f;
        g_acc2[n] = 0.0f;
    }
    gridbar();

    // ---- P1: degree REDs ----
    for (int i = tid; i < EV8; i += stride) {
        int4 a = __ldcs(&d4[i * 2]);
        int4 b = __ldcs(&d4[i * 2 + 1]);
        atomicAdd(&g_deg[a.x], 1.0f);
        atomicAdd(&g_deg[a.y], 1.0f);
        atomicAdd(&g_deg[a.z], 1.0f);
        atomicAdd(&g_deg[a.w], 1.0f);
        atomicAdd(&g_deg[b.x], 1.0f);
        atomicAdd(&g_deg[b.y], 1.0f);
        atomicAdd(&g_deg[b.z], 1.0f);
        atomicAdd(&g_deg[b.w], 1.0f);
    }
    if (tid == 0) {
        for (int e = EV8 * 8; e < E; ++e) atomicAdd(&g_deg[dst[e]], 1.0f);
    }
    gridbar();

    // ---- P2: dinv + hd16 ----
    for (int n = tid; n < N; n += stride) {
        float v  = __ldcg(&g_deg[n]);            // written via REDs -> read from L2
        float di = (v > 0.0f) ? rsqrtf(v) : 0.0f;
        g_dinv[n]  = di;
        g_hd16[n]  = __float2half_rn(g_h0[n] * di);
    }
    gridbar();

    // ---- P3: stage hd16 to smem, then pass1 REDs (skip exact zeros, 60%) ----
    {
        const uint4* gv = reinterpret_cast<const uint4*>(g_hd16);
        uint4* sv = reinterpret_cast<uint4*>(s_val);
        for (int i = threadIdx.x; i < (MAXN >> 3); i += NTHREADS)
            sv[i] = __ldcg(&gv[i]);              // cross-SM writes -> L2 read
    }
    __syncthreads();
    for (int i = tid; i < EV8; i += stride) {
        int4 sa = __ldcs(&s4[i * 2]);
        int4 sb = __ldcs(&s4[i * 2 + 1]);
        int4 da = __ldcs(&d4[i * 2]);
        int4 db = __ldcs(&d4[i * 2 + 1]);
        float v0 = __half2float(s_val[sa.x]);
        float v1 = __half2float(s_val[sa.y]);
        float v2 = __half2float(s_val[sa.z]);
        float v3 = __half2float(s_val[sa.w]);
        float v4 = __half2float(s_val[sb.x]);
        float v5 = __half2float(s_val[sb.y]);
        float v6 = __half2float(s_val[sb.z]);
        float v7 = __half2float(s_val[sb.w]);
        if (v0 != 0.0f) atomicAdd(&g_acc1[da.x], v0);
        if (v1 != 0.0f) atomicAdd(&g_acc1[da.y], v1);
        if (v2 != 0.0f) atomicAdd(&g_acc1[da.z], v2);
        if (v3 != 0.0f) atomicAdd(&g_acc1[da.w], v3);
        if (v4 != 0.0f) atomicAdd(&g_acc1[db.x], v4);
        if (v5 != 0.0f) atomicAdd(&g_acc1[db.y], v5);
        if (v6 != 0.0f) atomicAdd(&g_acc1[db.z], v6);
        if (v7 != 0.0f) atomicAdd(&g_acc1[db.w], v7);
    }
    if (tid == 0) {
        for (int e = EV8 * 8; e < E; ++e) {
            float v = __half2float(g_hd16[src[e]]);
            if (v != 0.0f) atomicAdd(&g_acc1[dst[e]], v);
        }
    }
    gridbar();

    // ---- P4: conv1 epilogue + relu + dropout2 + W2 contraction -> sd16 ----
    for (int n = tid; n < N; n += stride) {
        float a = __ldcg(&g_acc1[n]) * g_dinv[n];
        uint32_t base = (uint32_t)n * 16u;
        float s = 0.0f;
#pragma unroll
        for (int c = 0; c < 16; ++c) {
            uint32_t bits = rbits32(k2a, k2b, base + (uint32_t)c);
            float h = fmaf(a, __ldg(&W1[c]), __ldg(&b1[c]));
            h = fmaxf(h, 0.0f);
            if (bits < KEEP_THRESH)
                s = fmaf(h / 0.4f, __ldg(&W2[c]), s);
        }
        g_sd16[n] = __float2half_rn(s * g_dinv[n]);
    }
    gridbar();

    // ---- P5: stage sd16 to smem, then pass2 REDs ----
    {
        const uint4* gv = reinterpret_cast<const uint4*>(g_sd16);
        uint4* sv = reinterpret_cast<uint4*>(s_val);
        for (int i = threadIdx.x; i < (MAXN >> 3); i += NTHREADS)
            sv[i] = __ldcg(&gv[i]);
    }
    __syncthreads();
    for (int i = tid; i < EV8; i += stride) {
        int4 sa = __ldcs(&s4[i * 2]);
        int4 sb = __ldcs(&s4[i * 2 + 1]);
        int4 da = __ldcs(&d4[i * 2]);
        int4 db = __ldcs(&d4[i * 2 + 1]);
        float v0 = __half2float(s_val[sa.x]);
        float v1 = __half2float(s_val[sa.y]);
        float v2 = __half2float(s_val[sa.z]);
        float v3 = __half2float(s_val[sa.w]);
        float v4 = __half2float(s_val[sb.x]);
        float v5 = __half2float(s_val[sb.y]);
        float v6 = __half2float(s_val[sb.z]);
        float v7 = __half2float(s_val[sb.w]);
        atomicAdd(&g_acc2[da.x], v0);
        atomicAdd(&g_acc2[da.y], v1);
        atomicAdd(&g_acc2[da.z], v2);
        atomicAdd(&g_acc2[da.w], v3);
        atomicAdd(&g_acc2[db.x], v4);
        atomicAdd(&g_acc2[db.y], v5);
        atomicAdd(&g_acc2[db.z], v6);
        atomicAdd(&g_acc2[db.w], v7);
    }
    if (tid == 0) {
        for (int e = EV8 * 8; e < E; ++e)
            atomicAdd(&g_acc2[dst[e]], __half2float(g_sd16[src[e]]));
    }
    gridbar();

    // ---- P6: output ----
    for (int n = tid; n < N; n += stride)
        out[n] = fmaf(__ldcg(&g_acc2[n]), g_dinv[n], __ldg(&b2[0]));
}

// ---------------- host ----------------

extern "C" void kernel_launch(void* const* d_in, const int* in_sizes, int n_in,
                              void* d_out, int out_size) {
    const float* x   = (const float*)d_in[0];
    const int*   ei  = (const int*)d_in[1];      // edge_index is int32 (JAX x64 disabled)
    const float* W1  = (const float*)d_in[2];
    const float* b1  = (const float*)d_in[3];
    const float* W2  = (const float*)d_in[4];
    const float* b2  = (const float*)d_in[5];

    int N = in_sizes[0];
    int E = in_sizes[1] >> 1;
    if (N > MAXN || N <= 0 || E <= 0) return;

    const int* src = ei;
    const int* dst = ei + E;

    // key(42) -> (0, 42); partitionable split: key_i = threefry(parent, (0, i))
    uint32_t k1a, k1b, k2a, k2b;
    tf2x32(0u, 42u, 0u, 0u, k1a, k1b);
    tf2x32(0u, 42u, 0u, 1u, k2a, k2b);

    // opt-in to 196KB dynamic smem (attribute set; legal under graph capture)
    cudaFuncSetAttribute(k_fused, cudaFuncAttributeMaxDynamicSharedMemorySize, SMEM_BYTES);

    k_fused<<<NBLOCKS, NTHREADS, SMEM_BYTES>>>(x, src, dst, W1, b1, W2, b2,
                                               (float*)d_out, N, E,
                                               k1a, k1b, k2a, k2b);
}

// round 10
// speedup vs baseline: 2.4772x; 2.4772x over previous
#include <cuda_runtime.h>
#include <cuda_fp16.h>
#include <cstdint>

static constexpr int MAXN = 100352;              // multiple of 8
static constexpr int SMEM_BYTES = MAXN * 2;      // 196KB fp16 value array

// Scratch (static device globals: allocation-free per harness rules).
// INVARIANT: g_deg, g_acc1, g_acc2 are ZERO between runs. Established by
// module-load zero-init; maintained by each consumer kernel restoring zero
// after reading (k_hd -> deg, k_s2 -> acc1, k_final -> acc2). Deterministic:
// every run does identical work.
__device__ float  g_h0[MAXN];     // dropout1(x)
__device__ float  g_deg[MAXN];    // in-degree (float), zero-restored
__device__ float  g_dinv[MAXN];   // deg^-1/2 (0 if deg==0)
__device__ __half g_hd16[MAXN];   // h0 * dinv   (fp16)
__device__ float  g_acc1[MAXN];   // edge-sum for conv1, zero-restored
__device__ __half g_sd16[MAXN];   // s2 * dinv   (fp16)
__device__ float  g_acc2[MAXN];   // edge-sum for conv2, zero-restored

// keep  <=>  uniform(bits) < float32(0.4)  <=>  bits < 0x66666800
#define KEEP_THRESH 0x66666800u

__host__ __device__ __forceinline__ void tf2x32(uint32_t k0, uint32_t k1,
                                                uint32_t x0, uint32_t x1,
                                                uint32_t& o0, uint32_t& o1) {
    uint32_t ks2 = k0 ^ k1 ^ 0x1BD11BDAu;
    x0 += k0; x1 += k1;
#define TF_ROT(d) { x0 += x1; x1 = (x1 << (d)) | (x1 >> (32 - (d))); x1 ^= x0; }
    TF_ROT(13) TF_ROT(15) TF_ROT(26) TF_ROT(6)   x0 += k1;  x1 += ks2 + 1u;
    TF_ROT(17) TF_ROT(29) TF_ROT(16) TF_ROT(24)  x0 += ks2; x1 += k0 + 2u;
    TF_ROT(13) TF_ROT(15) TF_ROT(26) TF_ROT(6)   x0 += k0;  x1 += k1 + 3u;
    TF_ROT(17) TF_ROT(29) TF_ROT(16) TF_ROT(24)  x0 += k1;  x1 += ks2 + 4u;
    TF_ROT(13) TF_ROT(15) TF_ROT(26) TF_ROT(6)   x0 += ks2; x1 += k0 + 5u;
#undef TF_ROT
    o0 = x0; o1 = x1;
}

// partitionable counter-mode bits: lane0 ^ lane1 of threefry(key, (0, i))
__device__ __forceinline__ uint32_t rbits32(uint32_t k0, uint32_t k1, uint32_t i) {
    uint32_t a, b;
    tf2x32(k0, k1, 0u, i, a, b);
    return a ^ b;
}

// ---------------- kernels ----------------

// Fused: dropout1 init (node loop) + degree REDs (edge loop). Independent data;
// no internal ordering needed. g_deg enters zeroed (invariant).
__global__ __launch_bounds__(256) void k_initdeg(const float* __restrict__ x, int N,
                                                 const int* __restrict__ dst,
                                                 int EV, int E,
                                                 uint32_t k0, uint32_t k1) {
    int i = blockIdx.x * blockDim.x + threadIdx.x;
    if (i < N) {
        uint32_t bits = rbits32(k0, k1, (uint32_t)i);
        g_h0[i] = (bits < KEEP_THRESH) ? (x[i] / 0.4f) : 0.0f;
    }
    if (i < EV) {
        const int4* d4 = reinterpret_cast<const int4*>(dst);
        int4 a = __ldcs(&d4[i * 2]);
        int4 b = __ldcs(&d4[i * 2 + 1]);
        atomicAdd(&g_deg[a.x], 1.0f);
        atomicAdd(&g_deg[a.y], 1.0f);
        atomicAdd(&g_deg[a.z], 1.0f);
        atomicAdd(&g_deg[a.w], 1.0f);
        atomicAdd(&g_deg[b.x], 1.0f);
        atomicAdd(&g_deg[b.y], 1.0f);
        atomicAdd(&g_deg[b.z], 1.0f);
        atomicAdd(&g_deg[b.w], 1.0f);
    }
    if (i == 0) {
        for (int e = EV * 8; e < E; ++e) atomicAdd(&g_deg[dst[e]], 1.0f);
    }
}

__global__ __launch_bounds__(256) void k_hd(int N) {
    int n = blockIdx.x * blockDim.x + threadIdx.x;
    if (n >= N) return;
    float v  = g_deg[n];
    float di = (v > 0.0f) ? rsqrtf(v) : 0.0f;
    g_dinv[n]  = di;
    g_hd16[n]  = __float2half_rn(g_h0[n] * di);
    g_deg[n]   = 0.0f;                 // restore invariant for next run
}

// conv1 epilogue + relu + dropout2 (inline threefry) + W2 contraction
__global__ __launch_bounds__(256) void k_s2(const float* __restrict__ W1,
                                            const float* __restrict__ b1,
                                            const float* __restrict__ W2, int N,
                                            uint32_t k0, uint32_t k1) {
    int n = blockIdx.x * blockDim.x + threadIdx.x;
    if (n >= N) return;
    float a = g_acc1[n] * g_dinv[n];   // conv1 segment value (b1 added per channel)
    g_acc1[n] = 0.0f;                  // restore invariant for next run
    uint32_t base = (uint32_t)n * 16u;
    float s = 0.0f;
#pragma unroll
    for (int c = 0; c < 16; ++c) {
        uint32_t bits = rbits32(k0, k1, base + (uint32_t)c);
        float h = fmaf(a, __ldg(&W1[c]), __ldg(&b1[c]));
        h = fmaxf(h, 0.0f);
        if (bits < KEEP_THRESH)
            s = fmaf(h / 0.4f, __ldg(&W2[c]), s);
    }
    g_sd16[n] = __float2half_rn(s * g_dinv[n]);
}

__global__ __launch_bounds__(256) void k_final(float* __restrict__ out,
                                               const float* __restrict__ b2, int N) {
    int n = blockIdx.x * blockDim.x + threadIdx.x;
    if (n >= N) return;
    out[n] = fmaf(g_acc2[n], g_dinv[n], __ldg(&b2[0]));
    g_acc2[n] = 0.0f;                  // restore invariant for next run
}

// Scatter pass with the full fp16 value array staged in shared memory.
// One 1024-thread block per SM (196KB dynamic smem); LDS gathers replace
// spread global gathers. REDs stay global (REDG).
template <bool SKIP_ZERO>
__device__ __forceinline__ void scatter_smem(const int* __restrict__ src,
                                             const int* __restrict__ dst,
                                             int E, const __half* __restrict__ gval,
                                             float* __restrict__ acc) {
    extern __shared__ __half s_val[];
    {
        const uint4* gv = reinterpret_cast<const uint4*>(gval);
        uint4* sv = reinterpret_cast<uint4*>(s_val);
        for (int i = threadIdx.x; i < (MAXN >> 3); i += blockDim.x)
            sv[i] = gv[i];
    }
    __syncthreads();

    int EV = E >> 3;
    int stride = gridDim.x * blockDim.x;
    const int4* s4 = reinterpret_cast<const int4*>(src);
    const int4* d4 = reinterpret_cast<const int4*>(dst);
    for (int i = blockIdx.x * blockDim.x + threadIdx.x; i < EV; i += stride) {
        int4 sa = __ldcs(&s4[i * 2]);
        int4 sb = __ldcs(&s4[i * 2 + 1]);
        int4 da = __ldcs(&d4[i * 2]);
        int4 db = __ldcs(&d4[i * 2 + 1]);
        float v0 = __half2float(s_val[sa.x]);
        float v1 = __half2float(s_val[sa.y]);
        float v2 = __half2float(s_val[sa.z]);
        float v3 = __half2float(s_val[sa.w]);
        float v4 = __half2float(s_val[sb.x]);
        float v5 = __half2float(s_val[sb.y]);
        float v6 = __half2float(s_val[sb.z]);
        float v7 = __half2float(s_val[sb.w]);
        if (!SKIP_ZERO || v0 != 0.0f) atomicAdd(&acc[da.x], v0);
        if (!SKIP_ZERO || v1 != 0.0f) atomicAdd(&acc[da.y], v1);
        if (!SKIP_ZERO || v2 != 0.0f) atomicAdd(&acc[da.z], v2);
        if (!SKIP_ZERO || v3 != 0.0f) atomicAdd(&acc[da.w], v3);
        if (!SKIP_ZERO || v4 != 0.0f) atomicAdd(&acc[db.x], v4);
        if (!SKIP_ZERO || v5 != 0.0f) atomicAdd(&acc[db.y], v5);
        if (!SKIP_ZERO || v6 != 0.0f) atomicAdd(&acc[db.z], v6);
        if (!SKIP_ZERO || v7 != 0.0f) atomicAdd(&acc[db.w], v7);
    }
    if (blockIdx.x == 0 && threadIdx.x == 0) {
        for (int e = EV * 8; e < E; ++e) {
            float v = __half2float(s_val[src[e]]);
            if (!SKIP_ZERO || v != 0.0f) atomicAdd(&acc[dst[e]], v);
        }
    }
}

__global__ __launch_bounds__(1024) void k_pass1s(const int* __restrict__ src,
                                                 const int* __restrict__ dst, int E) {
    scatter_smem<true>(src, dst, E, g_hd16, g_acc1);   // 60% exact zeros -> skip
}

__global__ __launch_bounds__(1024) void k_pass2s(const int* __restrict__ src,
                                                 const int* __restrict__ dst, int E) {
    scatter_smem<false>(src, dst, E, g_sd16, g_acc2);  // ~all nonzero
}

// ---------------- host ----------------

extern "C" void kernel_launch(void* const* d_in, const int* in_sizes, int n_in,
                              void* d_out, int out_size) {
    const float* x   = (const float*)d_in[0];
    const int*   ei  = (const int*)d_in[1];      // edge_index is int32 (JAX x64 disabled)
    const float* W1  = (const float*)d_in[2];
    const float* b1  = (const float*)d_in[3];
    const float* W2  = (const float*)d_in[4];
    const float* b2  = (const float*)d_in[5];

    int N = in_sizes[0];
    int E = in_sizes[1] >> 1;
    if (N > MAXN || N <= 0 || E <= 0) return;

    const int* src = ei;
    const int* dst = ei + E;

    // key(42) -> (0, 42); partitionable split: key_i = threefry(parent, (0, i))
    uint32_t k1a, k1b, k2a, k2b;
    tf2x32(0u, 42u, 0u, 0u, k1a, k1b);
    tf2x32(0u, 42u, 0u, 1u, k2a, k2b);

    // opt-in to 196KB dynamic smem (attribute set; legal under graph capture)
    cudaFuncSetAttribute(k_pass1s, cudaFuncAttributeMaxDynamicSharedMemorySize, SMEM_BYTES);
    cudaFuncSetAttribute(k_pass2s, cudaFuncAttributeMaxDynamicSharedMemorySize, SMEM_BYTES);

    const int TPB = 256;
    int nb = (N + TPB - 1) / TPB;
    int EV8 = E / 8;
    int eb = (EV8 + TPB - 1) / TPB;
    if (eb == 0) eb = 1;
    int ib = (eb > nb) ? eb : nb;           // k_initdeg covers both index spaces

    k_initdeg<<<ib, TPB>>>(x, N, dst, EV8, E, k1a, k1b);
    k_hd     <<<nb, TPB>>>(N);
    k_pass1s <<<148, 1024, SMEM_BYTES>>>(src, dst, E);
    k_s2     <<<nb, TPB>>>(W1, b1, W2, N, k2a, k2b);
    k_pass2s <<<148, 1024, SMEM_BYTES>>>(src, dst, E);
    k_final  <<<nb, TPB>>>((float*)d_out, b2, N);
}